// round 9
// baseline (speedup 1.0000x reference)
#include <cuda_runtime.h>

// S2Conv, v4b: recompute strategy. Pass A = conv + stats (no store).
// Finalize. Pass B = conv again (x L2-resident) + scale/bias + relu + store.
// N=64, C=128, T=2048, S=9.

#define Nn 64
#define Cc 128
#define Tt 2048
#define Ss 9
#define CG 32          // output channels per block
#define ROWS 40        // CG + 8 halo
#define TBt 256        // time tile per block

__device__ float g_sum[Cc];
__device__ float g_sumsq[Cc];
__device__ float g_scale[Cc];
__device__ float g_bias[Cc];

__global__ void init_kernel() {
    int i = threadIdx.x;
    if (i < Cc) { g_sum[i] = 0.0f; g_sumsq[i] = 0.0f; }
}

// Weight loader: s_w[cl][s] for cl in [0,CG). CG*Ss=288 > 256 threads, so stride.
__device__ __forceinline__ void load_weights(
    float (*s_w)[12], const float* __restrict__ w, int cg0, int tid)
{
    for (int i = tid; i < CG * Ss; i += 256) {
        int cl = i / Ss, s = i % Ss;
        s_w[cl][s] = w[(cg0 + cl) * Ss + s];
    }
}

// Tile loader: tile[r][j] = xs[n, cg0-4+r, t0+j],
// xs[cc,t] = x[cc, t + 4 - cc%9], zero-padded outside [0,Tt).
__device__ __forceinline__ void load_tile(
    float (*tile)[TBt], const float* __restrict__ x,
    int n, int cg0, int t0, int tid)
{
    const float* xn = x + (size_t)n * Cc * Tt;
    #pragma unroll
    for (int k = 0; k < (ROWS * TBt / 4) / 256; k++) {   // 10 float4 per thread
        const int ci = tid + k * 256;
        const int r  = ci >> 6;               // TBt/4 = 64 float4 per row
        const int j  = (ci & 63) * 4;
        const int cc = cg0 - 4 + r;
        const bool rowok = (cc >= 0) && (cc < Cc);
        const int off = rowok ? (4 - (cc % 9)) : 0;
        const float* xr = xn + (size_t)(rowok ? cc : 0) * Tt;
        const int ts = t0 + j + off;
        float4 v = make_float4(0.f, 0.f, 0.f, 0.f);
        if (rowok) {
            if ((unsigned)(ts + 0) < (unsigned)Tt) v.x = __ldg(&xr[ts + 0]);
            if ((unsigned)(ts + 1) < (unsigned)Tt) v.y = __ldg(&xr[ts + 1]);
            if ((unsigned)(ts + 2) < (unsigned)Tt) v.z = __ldg(&xr[ts + 2]);
            if ((unsigned)(ts + 3) < (unsigned)Tt) v.w = __ldg(&xr[ts + 3]);
        }
        *reinterpret_cast<float4*>(&tile[r][j]) = v;
    }
}

// ---- Pass A: conv + per-channel stats, no output write.
__global__ __launch_bounds__(256) void stats_kernel(
    const float* __restrict__ x,
    const float* __restrict__ w)
{
    __shared__ float tile[ROWS][TBt];      // 40 KB
    __shared__ float s_w[CG][12];

    const int t0  = blockIdx.x * TBt;
    const int cg0 = blockIdx.y * CG;
    const int n   = blockIdx.z;
    const int tid = threadIdx.x;
    const int wid = tid >> 5;
    const int lane = tid & 31;
    const int lcb = wid * 4;               // warp -> channel quad

    load_weights(s_w, w, cg0, tid);
    load_tile(tile, x, n, cg0, t0, tid);
    __syncthreads();

    float lsum[4] = {0.f, 0.f, 0.f, 0.f};
    float lsq[4]  = {0.f, 0.f, 0.f, 0.f};

    #pragma unroll
    for (int it = 0; it < 2; it++) {
        const int j = it * 128 + lane * 4;
        float4 tp[12];
        #pragma unroll
        for (int r = 0; r < 12; r++)
            tp[r] = *reinterpret_cast<const float4*>(&tile[lcb + r][j]);
        #pragma unroll
        for (int cl = 0; cl < 4; cl++) {
            float4 a = make_float4(0.f, 0.f, 0.f, 0.f);
            #pragma unroll
            for (int s = 0; s < Ss; s++) {
                const float wv = s_w[lcb + cl][s];
                a.x = fmaf(wv, tp[cl + s].x, a.x);
                a.y = fmaf(wv, tp[cl + s].y, a.y);
                a.z = fmaf(wv, tp[cl + s].z, a.z);
                a.w = fmaf(wv, tp[cl + s].w, a.w);
            }
            lsum[cl] += (a.x + a.y) + (a.z + a.w);
            lsq[cl]   = fmaf(a.x, a.x, fmaf(a.y, a.y,
                        fmaf(a.z, a.z, fmaf(a.w, a.w, lsq[cl]))));
        }
    }

    #pragma unroll
    for (int cl = 0; cl < 4; cl++) {
        #pragma unroll
        for (int o = 16; o > 0; o >>= 1) {
            lsum[cl] += __shfl_down_sync(0xffffffffu, lsum[cl], o);
            lsq[cl]  += __shfl_down_sync(0xffffffffu, lsq[cl],  o);
        }
    }
    if (lane == 0) {
        #pragma unroll
        for (int cl = 0; cl < 4; cl++) {
            atomicAdd(&g_sum[cg0 + lcb + cl],   lsum[cl]);
            atomicAdd(&g_sumsq[cg0 + lcb + cl], lsq[cl]);
        }
    }
}

// ---- Finalize: per-channel scale/bias.
__global__ void finalize_kernel(const float* __restrict__ gamma,
                                const float* __restrict__ beta)
{
    int c = threadIdx.x;
    if (c >= Cc) return;
    const float inv = 1.0f / ((float)Nn * (float)Tt);
    float mean = g_sum[c] * inv;
    float var  = g_sumsq[c] * inv - mean * mean;
    float rstd = rsqrtf(var + 1e-5f);
    float sc   = gamma[c] * rstd;
    g_scale[c] = sc;
    g_bias[c]  = beta[c] - mean * sc;
}

// ---- Pass B: conv again + normalize + relu + store.
__global__ __launch_bounds__(256) void conv_out_kernel(
    const float* __restrict__ x,
    const float* __restrict__ w,
    float* __restrict__ out)
{
    __shared__ float tile[ROWS][TBt];
    __shared__ float s_w[CG][12];
    __shared__ float s_scale[CG], s_bias[CG];

    const int t0  = blockIdx.x * TBt;
    const int cg0 = blockIdx.y * CG;
    const int n   = blockIdx.z;
    const int tid = threadIdx.x;
    const int wid = tid >> 5;
    const int lane = tid & 31;
    const int lcb = wid * 4;

    load_weights(s_w, w, cg0, tid);
    if (tid < CG) {
        s_scale[tid] = g_scale[cg0 + tid];
        s_bias[tid]  = g_bias[cg0 + tid];
    }
    load_tile(tile, x, n, cg0, t0, tid);
    __syncthreads();

    float* outb = out + ((size_t)n * Cc + cg0 + lcb) * Tt + t0;
    #pragma unroll
    for (int it = 0; it < 2; it++) {
        const int j = it * 128 + lane * 4;
        float4 tp[12];
        #pragma unroll
        for (int r = 0; r < 12; r++)
            tp[r] = *reinterpret_cast<const float4*>(&tile[lcb + r][j]);
        #pragma unroll
        for (int cl = 0; cl < 4; cl++) {
            float4 a = make_float4(0.f, 0.f, 0.f, 0.f);
            #pragma unroll
            for (int s = 0; s < Ss; s++) {
                const float wv = s_w[lcb + cl][s];
                a.x = fmaf(wv, tp[cl + s].x, a.x);
                a.y = fmaf(wv, tp[cl + s].y, a.y);
                a.z = fmaf(wv, tp[cl + s].z, a.z);
                a.w = fmaf(wv, tp[cl + s].w, a.w);
            }
            const float sc = s_scale[lcb + cl];
            const float bs = s_bias[lcb + cl];
            a.x = fmaxf(fmaf(a.x, sc, bs), 0.0f);
            a.y = fmaxf(fmaf(a.y, sc, bs), 0.0f);
            a.z = fmaxf(fmaf(a.z, sc, bs), 0.0f);
            a.w = fmaxf(fmaf(a.w, sc, bs), 0.0f);
            *reinterpret_cast<float4*>(outb + (size_t)cl * Tt + j) = a;
        }
    }
}

extern "C" void kernel_launch(void* const* d_in, const int* in_sizes, int n_in,
                              void* d_out, int out_size)
{
    const float* x     = (const float*)d_in[0];
    const float* w     = (const float*)d_in[1];
    const float* gamma = (const float*)d_in[2];
    const float* beta  = (const float*)d_in[3];
    float* out = (float*)d_out;

    const dim3 grid(Tt / TBt, Cc / CG, Nn);   // 8 x 4 x 64 = 2048 blocks
    init_kernel<<<1, 128>>>();
    stats_kernel<<<grid, 256>>>(x, w);
    finalize_kernel<<<1, 128>>>(gamma, beta);
    conv_out_kernel<<<grid, 256>>>(x, w, out);
}